// round 14
// baseline (speedup 1.0000x reference)
#include <cuda_runtime.h>
#include <cuda_bf16.h>
#include <cuda_fp16.h>
#include <cstdint>
#include <cstddef>

// ===========================================================================
// RelativeAttention on sm_100 (plain target: legacy mma.sync / HMMA).
// R14: proj -> 128x64 tiles (wave-quantization fix: 640->1280 CTAs),
//      merged prep launch (input split + all transposes in one grid).
//
//   1) prep (one launch): split {x,anchors} -> bf16 hi/lo;
//      transpose+split Wq, Wk (bf16); values -> Vt fp16
//   2) {Qf, Kf} = {x@Wq, anchors@Wk}   (one 3-term bf16 mma launch, 128x64)
//   3) l2norm (one launch): Q -> fp16 qhat (+den=0); K -> fp16 khat
//   4) SIM (1-term fp16): quant->exp -> E fp16 + rowsum atomics
//   5) OUT (1-term fp16): O = E @ Vt^T -> scale 1/den -> fp32 out
// ===========================================================================

// ------------------------- device scratch ----------------------------------
__device__ float g_Qf[16384 * 512];
__device__ float g_Kf[4096 * 512];
__device__ float g_den[16384];
__device__ __nv_bfloat16 g_xhi[16384 * 512];
__device__ __nv_bfloat16 g_xlo[16384 * 512];
__device__ __nv_bfloat16 g_ahi[4096 * 512];
__device__ __nv_bfloat16 g_alo[4096 * 512];
__device__ __nv_bfloat16 g_Wqthi[512 * 512];
__device__ __nv_bfloat16 g_Wqtlo[512 * 512];
__device__ __nv_bfloat16 g_Wkthi[512 * 512];
__device__ __nv_bfloat16 g_Wktlo[512 * 512];
__device__ __half g_Qh[16384 * 512];
__device__ __half g_Kh[4096 * 512];
__device__ __half g_E[(size_t)16384 * 4096];
__device__ __half g_Vt[512 * 4096];

// ------------------------- helpers -----------------------------------------
__device__ __forceinline__ uint32_t s2u(const void* p) {
    uint32_t a;
    asm("{ .reg .u64 t; cvta.to.shared.u64 t, %1; cvt.u32.u64 %0, t; }"
        : "=r"(a) : "l"(p));
    return a;
}

__device__ __forceinline__ void cp16(uint32_t dst, const void* src) {
    asm volatile("cp.async.cg.shared.global [%0], [%1], 16;" :: "r"(dst), "l"(src));
}
#define CP_COMMIT() asm volatile("cp.async.commit_group;" ::: "memory")
#define CP_WAIT1()  asm volatile("cp.async.wait_group 1;" ::: "memory")

__device__ __forceinline__ void ldsm4(uint32_t* r, uint32_t addr) {
    asm volatile("ldmatrix.sync.aligned.m8n8.x4.shared.b16 {%0,%1,%2,%3}, [%4];"
        : "=r"(r[0]), "=r"(r[1]), "=r"(r[2]), "=r"(r[3]) : "r"(addr));
}

__device__ __forceinline__ void mma_bf16(float* d, const uint32_t* a, const uint32_t* b) {
    asm volatile(
        "mma.sync.aligned.m16n8k16.row.col.f32.bf16.bf16.f32 "
        "{%0,%1,%2,%3}, {%4,%5,%6,%7}, {%8,%9}, {%0,%1,%2,%3};"
        : "+f"(d[0]), "+f"(d[1]), "+f"(d[2]), "+f"(d[3])
        : "r"(a[0]), "r"(a[1]), "r"(a[2]), "r"(a[3]), "r"(b[0]), "r"(b[1]));
}

__device__ __forceinline__ void mma_f16(float* d, const uint32_t* a, const uint32_t* b) {
    asm volatile(
        "mma.sync.aligned.m16n8k16.row.col.f32.f16.f16.f32 "
        "{%0,%1,%2,%3}, {%4,%5,%6,%7}, {%8,%9}, {%0,%1,%2,%3};"
        : "+f"(d[0]), "+f"(d[1]), "+f"(d[2]), "+f"(d[3])
        : "r"(a[0]), "r"(a[1]), "r"(a[2]), "r"(a[3]), "r"(b[0]), "r"(b[1]));
}

__device__ __forceinline__ uint32_t pack_bf2(float a, float b) {
    __nv_bfloat16 ha = __float2bfloat16(a), hb = __float2bfloat16(b);
    return (uint32_t)__bfloat16_as_ushort(ha) |
           ((uint32_t)__bfloat16_as_ushort(hb) << 16);
}
__device__ __forceinline__ uint32_t pack_h2(float a, float b) {
    __half2 h = __floats2half2_rn(a, b);
    return *(uint32_t*)&h;
}

// ------------------------- tiling constants ---------------------------------
#define ROWB 80
#define TILEB (128 * ROWB)              // 10240 (128-row tile)
#define BT64  (64 * ROWB)               // 5120  (64-row tile)
#define STAGE_P (2 * TILEB + 2 * BT64)  // proj: Ahi,Alo(128r) + Bhi,Blo(64r) = 30720
#define STAGE2T (2 * TILEB)             // sim/out: A,B
static constexpr int SMEM_P = 2 * STAGE_P;   // 61440
static constexpr int SMEM2T = 2 * STAGE2T;   // 40960

// ------------------------- stage loaders ------------------------------------
// proj (128x64): units: [0,512) Ahi, [512,1024) Alo, [1024,1280) Bhi, [1280,1536) Blo
__device__ __forceinline__ void load_stage_p(
    uint32_t sbase, const __nv_bfloat16* Ahi, const __nv_bfloat16* Alo,
    const __nv_bfloat16* Bhi, const __nv_bfloat16* Blo,
    int bm0, int bn0, int K, int c, int tid)
{
    const size_t kb = (size_t)c * 32;
#pragma unroll
    for (int t = 0; t < 6; t++) {
        const int u = tid + t * 256;
        const __nv_bfloat16* g;
        int row; uint32_t dst; int w;
        if (u < 512)        { g = Ahi; w = u;        row = bm0 + (w >> 2);
                              dst = sbase + (w >> 2) * ROWB; }
        else if (u < 1024)  { g = Alo; w = u - 512;  row = bm0 + (w >> 2);
                              dst = sbase + TILEB + (w >> 2) * ROWB; }
        else if (u < 1280)  { g = Bhi; w = u - 1024; row = bn0 + (w >> 2);
                              dst = sbase + 2 * TILEB + (w >> 2) * ROWB; }
        else                { g = Blo; w = u - 1280; row = bn0 + (w >> 2);
                              dst = sbase + 2 * TILEB + BT64 + (w >> 2) * ROWB; }
        const int c16 = w & 3;
        cp16(dst + c16 * 16, g + (size_t)row * K + kb + c16 * 8);
    }
}

__device__ __forceinline__ void load_stage2(
    uint32_t sbase, const __half* A, const __half* B,
    int bm0, int bn0, int K, int c, int tid)
{
    const __half* gp[2] = { A, B };
    const int rb[2] = { bm0, bn0 };
    const size_t kb = (size_t)c * 32;
#pragma unroll
    for (int t = 0; t < 4; t++) {
        const int seg  = tid + t * 256;
        const int tile = seg >> 9;
        const int w    = seg & 511;
        const int row  = w >> 2;
        const int c16  = w & 3;
        const __half* src = gp[tile] + (size_t)(rb[tile] + row) * K + kb + c16 * 8;
        cp16(sbase + tile * TILEB + row * ROWB + c16 * 16, src);
    }
}

// ------------------- merged 3-term bf16 projection GEMM (128x64) ------------
// One launch: Qf = x@Wq (blocks y < nby_x) and Kf = anchors@Wk.
// 8 warps (4 M x 2 N), warp tile 32x32.
__global__ __launch_bounds__(256, 2)
void proj3_dual_kernel(const __nv_bfloat16* __restrict__ Xhi,
                       const __nv_bfloat16* __restrict__ Xlo,
                       const __nv_bfloat16* __restrict__ WQhi,
                       const __nv_bfloat16* __restrict__ WQlo,
                       float* __restrict__ Cq,
                       const __nv_bfloat16* __restrict__ AHi,
                       const __nv_bfloat16* __restrict__ ALo,
                       const __nv_bfloat16* __restrict__ WKhi,
                       const __nv_bfloat16* __restrict__ WKlo,
                       float* __restrict__ Ck,
                       int nby_x, int K, int ldC)
{
    extern __shared__ char sm[];
    const uint32_t sb = s2u(sm);
    const int tid  = threadIdx.x;
    const int wid  = tid >> 5;
    const int lane = tid & 31;
    const int wm   = wid >> 1;          // 0..3 (M, 32 rows)
    const int wn   = wid & 1;           // 0..1 (N, 32 cols)
    const int g    = lane >> 2;
    const int tg   = lane & 3;

    const bool is_x = ((int)blockIdx.y < nby_x);
    const int bm0 = (is_x ? blockIdx.y : blockIdx.y - nby_x) * 128;
    const int bn0 = blockIdx.x * 64;
    const __nv_bfloat16* Ahi = is_x ? Xhi  : AHi;
    const __nv_bfloat16* Alo = is_x ? Xlo  : ALo;
    const __nv_bfloat16* Bhi = is_x ? WQhi : WKhi;
    const __nv_bfloat16* Blo = is_x ? WQlo : WKlo;
    float* Cf = is_x ? Cq : Ck;

    const int grp  = lane >> 3;
    const int lrow = lane & 7;
    const uint32_t a_off = (uint32_t)((wm * 32 + lrow + ((grp & 1) << 3)) * ROWB
                                      + ((grp >> 1) << 4));
    const uint32_t b_off = (uint32_t)((wn * 32 + lrow + ((grp >> 1) << 3)) * ROWB
                                      + ((grp & 1) << 4));

    float acc[2][4][4];
#pragma unroll
    for (int mt = 0; mt < 2; mt++)
#pragma unroll
        for (int nt = 0; nt < 4; nt++)
#pragma unroll
            for (int j = 0; j < 4; j++) acc[mt][nt][j] = 0.f;

    const int nch = K >> 5;
    load_stage_p(sb,           Ahi, Alo, Bhi, Blo, bm0, bn0, K, 0, tid);
    CP_COMMIT();
    load_stage_p(sb + STAGE_P, Ahi, Alo, Bhi, Blo, bm0, bn0, K, 1, tid);
    CP_COMMIT();

    for (int c = 0; c < nch; c++) {
        CP_WAIT1();
        __syncthreads();
        const uint32_t st = sb + (c & 1) * STAGE_P;

#pragma unroll
        for (int ks = 0; ks < 2; ks++) {
            const uint32_t kk = ks * 32;
            uint32_t ah[2][4], al[2][4], bh[2][4], bl[2][4];
#pragma unroll
            for (int mt = 0; mt < 2; mt++) {
                ldsm4(ah[mt], st + a_off + mt * (16 * ROWB) + kk);
                ldsm4(al[mt], st + TILEB + a_off + mt * (16 * ROWB) + kk);
            }
#pragma unroll
            for (int np = 0; np < 2; np++) {
                ldsm4(bh[np], st + 2 * TILEB + b_off + np * (16 * ROWB) + kk);
                ldsm4(bl[np], st + 2 * TILEB + BT64 + b_off + np * (16 * ROWB) + kk);
            }
#pragma unroll
            for (int np = 0; np < 2; np++)
#pragma unroll
                for (int sub = 0; sub < 2; sub++)
#pragma unroll
                    for (int mt = 0; mt < 2; mt++) {
                        mma_bf16(acc[mt][np * 2 + sub], ah[mt], &bh[np][2 * sub]);
                        mma_bf16(acc[mt][np * 2 + sub], ah[mt], &bl[np][2 * sub]);
                        mma_bf16(acc[mt][np * 2 + sub], al[mt], &bh[np][2 * sub]);
                    }
        }
        __syncthreads();
        if (c + 2 < nch)
            load_stage_p(sb + (c & 1) * STAGE_P, Ahi, Alo, Bhi, Blo, bm0, bn0, K, c + 2, tid);
        CP_COMMIT();
    }

#pragma unroll
    for (int mt = 0; mt < 2; mt++) {
        const int rh = bm0 + wm * 32 + mt * 16 + g;
        const int rl = rh + 8;
#pragma unroll
        for (int nt = 0; nt < 4; nt++) {
            const int col = bn0 + wn * 32 + nt * 8 + tg * 2;
            *(float2*)(Cf + (size_t)rh * ldC + col) =
                make_float2(acc[mt][nt][0], acc[mt][nt][1]);
            *(float2*)(Cf + (size_t)rl * ldC + col) =
                make_float2(acc[mt][nt][2], acc[mt][nt][3]);
        }
    }
}

// ------------------------- 1-term fp16 SIM kernel ---------------------------
__global__ __launch_bounds__(256, 2)
void sim1_kernel(const __half* __restrict__ Qh,
                 const __half* __restrict__ Kh,
                 int K, int ldC,
                 float* __restrict__ den,
                 __half* __restrict__ E)
{
    extern __shared__ char sm[];
    const uint32_t sb = s2u(sm);
    const int tid  = threadIdx.x;
    const int wid  = tid >> 5;
    const int lane = tid & 31;
    const int wm   = wid >> 1;
    const int wn   = wid & 1;
    const int g    = lane >> 2;
    const int tg   = lane & 3;
    const int bm0  = blockIdx.y * 128;
    const int bn0  = blockIdx.x * 128;

    const int grp  = lane >> 3;
    const int lrow = lane & 7;
    const uint32_t a_off = (uint32_t)((wm * 32 + lrow + ((grp & 1) << 3)) * ROWB
                                      + ((grp >> 1) << 4));
    const uint32_t b_off = (uint32_t)((wn * 64 + lrow + ((grp >> 1) << 3)) * ROWB
                                      + ((grp & 1) << 4));

    float acc[2][8][4];
#pragma unroll
    for (int mt = 0; mt < 2; mt++)
#pragma unroll
        for (int nt = 0; nt < 8; nt++)
#pragma unroll
            for (int j = 0; j < 4; j++) acc[mt][nt][j] = 0.f;

    const int nch = K >> 5;   // 16
    load_stage2(sb,           Qh, Kh, bm0, bn0, K, 0, tid);
    CP_COMMIT();
    load_stage2(sb + STAGE2T, Qh, Kh, bm0, bn0, K, 1, tid);
    CP_COMMIT();

    for (int c = 0; c < nch; c++) {
        CP_WAIT1();
        __syncthreads();
        const uint32_t st = sb + (c & 1) * STAGE2T;

#pragma unroll
        for (int ks = 0; ks < 2; ks++) {
            const uint32_t kk = ks * 32;
            uint32_t ah[2][4], bh[4][4];
#pragma unroll
            for (int mt = 0; mt < 2; mt++)
                ldsm4(ah[mt], st + a_off + mt * (16 * ROWB) + kk);
#pragma unroll
            for (int np = 0; np < 4; np++)
                ldsm4(bh[np], st + TILEB + b_off + np * (16 * ROWB) + kk);
#pragma unroll
            for (int np = 0; np < 4; np++)
#pragma unroll
                for (int sub = 0; sub < 2; sub++)
#pragma unroll
                    for (int mt = 0; mt < 2; mt++)
                        mma_f16(acc[mt][np * 2 + sub], ah[mt], &bh[np][2 * sub]);
        }
        __syncthreads();
        if (c + 2 < nch)
            load_stage2(sb + (c & 1) * STAGE2T, Qh, Kh, bm0, bn0, K, c + 2, tid);
        CP_COMMIT();
    }

    // epilogue: quantize -> exp -> E fp16 + rowsum atomics
    float rs[2][2] = { {0.f, 0.f}, {0.f, 0.f} };
#pragma unroll
    for (int mt = 0; mt < 2; mt++) {
        const int rh = bm0 + wm * 32 + mt * 16 + g;
        const int rl = rh + 8;
#pragma unroll
        for (int nt = 0; nt < 8; nt++) {
            const int col = bn0 + wn * 64 + nt * 8 + tg * 2;
            float e0 = __expf(rintf(acc[mt][nt][0] / 0.05f) * 0.05f);
            float e1 = __expf(rintf(acc[mt][nt][1] / 0.05f) * 0.05f);
            float e2 = __expf(rintf(acc[mt][nt][2] / 0.05f) * 0.05f);
            float e3 = __expf(rintf(acc[mt][nt][3] / 0.05f) * 0.05f);
            rs[mt][0] += e0 + e1;
            rs[mt][1] += e2 + e3;
            *(uint32_t*)(E + (size_t)rh * ldC + col) = pack_h2(e0, e1);
            *(uint32_t*)(E + (size_t)rl * ldC + col) = pack_h2(e2, e3);
        }
    }
#pragma unroll
    for (int mt = 0; mt < 2; mt++)
#pragma unroll
        for (int hl = 0; hl < 2; hl++) {
            float v = rs[mt][hl];
            v += __shfl_xor_sync(0xffffffffu, v, 1);
            v += __shfl_xor_sync(0xffffffffu, v, 2);
            if (tg == 0)
                atomicAdd(&den[bm0 + wm * 32 + mt * 16 + g + hl * 8], v);
        }
}

// ------------------------- 1-term fp16 OUT kernel ---------------------------
__global__ __launch_bounds__(256, 2)
void out1_kernel(const __half* __restrict__ E,
                 const __half* __restrict__ Vt,
                 int K, int ldC,
                 const float* __restrict__ den,
                 float* __restrict__ Cf)
{
    extern __shared__ char sm[];
    const uint32_t sb = s2u(sm);
    const int tid  = threadIdx.x;
    const int wid  = tid >> 5;
    const int lane = tid & 31;
    const int wm   = wid >> 1;
    const int wn   = wid & 1;
    const int g    = lane >> 2;
    const int tg   = lane & 3;
    const int bm0  = blockIdx.y * 128;
    const int bn0  = blockIdx.x * 128;

    const int grp  = lane >> 3;
    const int lrow = lane & 7;
    const uint32_t a_off = (uint32_t)((wm * 32 + lrow + ((grp & 1) << 3)) * ROWB
                                      + ((grp >> 1) << 4));
    const uint32_t b_off = (uint32_t)((wn * 64 + lrow + ((grp >> 1) << 3)) * ROWB
                                      + ((grp & 1) << 4));

    float acc[2][8][4];
#pragma unroll
    for (int mt = 0; mt < 2; mt++)
#pragma unroll
        for (int nt = 0; nt < 8; nt++)
#pragma unroll
            for (int j = 0; j < 4; j++) acc[mt][nt][j] = 0.f;

    const int nch = K >> 5;   // 128
    load_stage2(sb,           E, Vt, bm0, bn0, K, 0, tid);
    CP_COMMIT();
    load_stage2(sb + STAGE2T, E, Vt, bm0, bn0, K, 1, tid);
    CP_COMMIT();

    for (int c = 0; c < nch; c++) {
        CP_WAIT1();
        __syncthreads();
        const uint32_t st = sb + (c & 1) * STAGE2T;

#pragma unroll
        for (int ks = 0; ks < 2; ks++) {
            const uint32_t kk = ks * 32;
            uint32_t ah[2][4], bh[4][4];
#pragma unroll
            for (int mt = 0; mt < 2; mt++)
                ldsm4(ah[mt], st + a_off + mt * (16 * ROWB) + kk);
#pragma unroll
            for (int np = 0; np < 4; np++)
                ldsm4(bh[np], st + TILEB + b_off + np * (16 * ROWB) + kk);
#pragma unroll
            for (int np = 0; np < 4; np++)
#pragma unroll
                for (int sub = 0; sub < 2; sub++)
#pragma unroll
                    for (int mt = 0; mt < 2; mt++)
                        mma_f16(acc[mt][np * 2 + sub], ah[mt], &bh[np][2 * sub]);
        }
        __syncthreads();
        if (c + 2 < nch)
            load_stage2(sb + (c & 1) * STAGE2T, E, Vt, bm0, bn0, K, c + 2, tid);
        CP_COMMIT();
    }

#pragma unroll
    for (int mt = 0; mt < 2; mt++) {
        const int rh = bm0 + wm * 32 + mt * 16 + g;
        const int rl = rh + 8;
        const float sh = 1.0f / den[rh];
        const float sl = 1.0f / den[rl];
#pragma unroll
        for (int nt = 0; nt < 8; nt++) {
            const int col = bn0 + wn * 64 + nt * 8 + tg * 2;
            *(float2*)(Cf + (size_t)rh * ldC + col) =
                make_float2(acc[mt][nt][0] * sh, acc[mt][nt][1] * sh);
            *(float2*)(Cf + (size_t)rl * ldC + col) =
                make_float2(acc[mt][nt][2] * sl, acc[mt][nt][3] * sl);
        }
    }
}

// ---------------- merged prep: input split + all transposes -----------------
// blocks [0, nsplit): split {x, anchors} -> bf16 hi/lo (flat indexing)
// blocks [nsplit, nsplit + 16*(16+16+128)): transpose Wq/Wk (bf16 split), V (fp16)
__global__ void prep_kernel(const float* __restrict__ x,
                            __nv_bfloat16* __restrict__ xhi,
                            __nv_bfloat16* __restrict__ xlo,
                            int n4x,
                            const float* __restrict__ a,
                            __nv_bfloat16* __restrict__ ahi,
                            __nv_bfloat16* __restrict__ alo,
                            int n4a, int nsplit,
                            const float* __restrict__ Wq,
                            __nv_bfloat16* __restrict__ Wqthi,
                            __nv_bfloat16* __restrict__ Wqtlo,
                            const float* __restrict__ Wk,
                            __nv_bfloat16* __restrict__ Wkthi,
                            __nv_bfloat16* __restrict__ Wktlo,
                            const float* __restrict__ V,
                            __half* __restrict__ Vt)
{
    __shared__ float t[32][33];
    const int bid = blockIdx.x;
    const int tid = threadIdx.x;

    if (bid < nsplit) {
        int i = bid * 256 + tid;
        const float* s;
        __nv_bfloat16 *hi, *lo;
        if (i < n4x) { s = x; hi = xhi; lo = xlo; }
        else {
            i -= n4x;
            if (i >= n4a) return;
            s = a; hi = ahi; lo = alo;
        }
        float4 v = ((const float4*)s)[i];
        const float f[4] = { v.x, v.y, v.z, v.w };
        uint32_t hp[2], lp[2];
#pragma unroll
        for (int j = 0; j < 2; j++) {
            __nv_bfloat16 h0 = __float2bfloat16(f[2 * j]);
            __nv_bfloat16 h1 = __float2bfloat16(f[2 * j + 1]);
            hp[j] = (uint32_t)__bfloat16_as_ushort(h0) |
                    ((uint32_t)__bfloat16_as_ushort(h1) << 16);
            lp[j] = pack_bf2(f[2 * j]     - __bfloat162float(h0),
                             f[2 * j + 1] - __bfloat162float(h1));
        }
        *(uint2*)(hi + (size_t)i * 4) = make_uint2(hp[0], hp[1]);
        *(uint2*)(lo + (size_t)i * 4) = make_uint2(lp[0], lp[1]);
        return;
    }

    // transpose path
    const int b  = bid - nsplit;
    const int bx = b & 15;          // 16 column-blocks (C = 512)
    const int by = b >> 4;
    const float* src;
    __nv_bfloat16 *hi = nullptr, *lo = nullptr;
    int mode, byl, R;
    if (by < 16)      { src = Wq; hi = Wqthi; lo = Wqtlo; R = 512;  mode = 0; byl = by; }
    else if (by < 32) { src = Wk; hi = Wkthi; lo = Wktlo; R = 512;  mode = 0; byl = by - 16; }
    else              { src = V;                          R = 4096; mode = 1; byl = by - 32; }
    const int C = 512;
    const int c0 = bx * 32, r0 = byl * 32;
    const int tx = tid & 31, ty = tid >> 5;   // 32 x 8
#pragma unroll
    for (int j = 0; j < 32; j += 8)
        t[ty + j][tx] = src[(size_t)(r0 + ty + j) * C + c0 + tx];
    __syncthreads();
    if (mode == 0) {
#pragma unroll
        for (int j = 0; j < 32; j += 8) {
            const float v = t[tx][ty + j];
            __nv_bfloat16 h = __float2bfloat16(v);
            const size_t o = (size_t)(c0 + ty + j) * R + r0 + tx;
            hi[o] = h;
            lo[o] = __float2bfloat16(v - __bfloat162float(h));
        }
    } else {
#pragma unroll
        for (int j = 0; j < 32; j += 8)
            Vt[(size_t)(c0 + ty + j) * R + r0 + tx] = __float2half_rn(t[tx][ty + j]);
    }
}

// ------------------------- merged l2 normalize ------------------------------
__global__ void l2norm_dual_kernel(const float* __restrict__ Qf,
                                   __half* __restrict__ Qh,
                                   float* __restrict__ den,
                                   int B,
                                   const float* __restrict__ Kf,
                                   __half* __restrict__ Kh)
{
    const int blk = blockIdx.x;
    const bool isQ = (blk < B);
    const int r = isQ ? blk : blk - B;
    const float* P = isQ ? Qf : Kf;
    const int t = threadIdx.x;  // 128 threads x float4 (H=512)
    const float4 v = ((const float4*)(P + (size_t)r * 512))[t];
    float ss = v.x * v.x + v.y * v.y + v.z * v.z + v.w * v.w;
#pragma unroll
    for (int m = 16; m; m >>= 1) ss += __shfl_xor_sync(0xffffffffu, ss, m);
    __shared__ float ws[4];
    if ((t & 31) == 0) ws[t >> 5] = ss;
    __syncthreads();
    const float d = fmaxf(sqrtf(ws[0] + ws[1] + ws[2] + ws[3]), 1e-12f);
    uint32_t hp[2];
    hp[0] = pack_h2(v.x / d, v.y / d);
    hp[1] = pack_h2(v.z / d, v.w / d);
    __half* dst = isQ ? Qh : Kh;
    *(uint2*)(dst + (size_t)r * 512 + t * 4) = make_uint2(hp[0], hp[1]);
    if (isQ && t == 0) den[r] = 0.f;
}

// ------------------------- launch -------------------------------------------
extern "C" void kernel_launch(void* const* d_in, const int* in_sizes, int n_in,
                              void* d_out, int out_size)
{
    const float* x       = (const float*)d_in[0];
    const float* anchors = (const float*)d_in[1];
    const float* Wq      = (const float*)d_in[2];
    const float* Wk      = (const float*)d_in[3];
    const float* values  = (const float*)d_in[4];
    float* out = (float*)d_out;

    const int D = 512, H = 512;
    const int B = in_sizes[0] / D;   // 16384
    const int A = in_sizes[1] / D;   // 4096

    float *Qf, *Kf, *dn;
    __nv_bfloat16 *xhi, *xlo, *ahi, *alo, *Wqthi, *Wqtlo, *Wkthi, *Wktlo;
    __half *Qh, *Kh, *E, *Vt;
    cudaGetSymbolAddress((void**)&Qf,    g_Qf);
    cudaGetSymbolAddress((void**)&Kf,    g_Kf);
    cudaGetSymbolAddress((void**)&dn,    g_den);
    cudaGetSymbolAddress((void**)&xhi,   g_xhi);
    cudaGetSymbolAddress((void**)&xlo,   g_xlo);
    cudaGetSymbolAddress((void**)&ahi,   g_ahi);
    cudaGetSymbolAddress((void**)&alo,   g_alo);
    cudaGetSymbolAddress((void**)&Wqthi, g_Wqthi);
    cudaGetSymbolAddress((void**)&Wqtlo, g_Wqtlo);
    cudaGetSymbolAddress((void**)&Wkthi, g_Wkthi);
    cudaGetSymbolAddress((void**)&Wktlo, g_Wktlo);
    cudaGetSymbolAddress((void**)&Qh,    g_Qh);
    cudaGetSymbolAddress((void**)&Kh,    g_Kh);
    cudaGetSymbolAddress((void**)&E,     g_E);
    cudaGetSymbolAddress((void**)&Vt,    g_Vt);

    cudaFuncSetAttribute(proj3_dual_kernel,
                         cudaFuncAttributeMaxDynamicSharedMemorySize, SMEM_P);
    cudaFuncSetAttribute(sim1_kernel,
                         cudaFuncAttributeMaxDynamicSharedMemorySize, SMEM2T);
    cudaFuncSetAttribute(out1_kernel,
                         cudaFuncAttributeMaxDynamicSharedMemorySize, SMEM2T);

    // 1) merged prep: input splits + W/V transposes in ONE launch
    const int n4x = B * D / 4, n4a = A * D / 4;
    const int nsplit = (n4x + n4a + 255) / 256;
    const int ntrans = 16 * (16 + 16 + A / 32);
    prep_kernel<<<nsplit + ntrans, 256>>>(
        x, xhi, xlo, n4x, anchors, ahi, alo, n4a, nsplit,
        Wq, Wqthi, Wqtlo, Wk, Wkthi, Wktlo, values, Vt);

    // 2) both projections in one launch (128x64 tiles -> 1280 CTAs)
    proj3_dual_kernel<<<dim3(H / 64, B / 128 + A / 128), 256, SMEM_P>>>(
        xhi, xlo, Wqthi, Wqtlo, Qf,
        ahi, alo, Wkthi, Wktlo, Kf,
        B / 128, D, H);

    // 3) merged l2 normalize (Q fp16 + den=0; K fp16)
    l2norm_dual_kernel<<<B + A, 128>>>(Qf, Qh, dn, B, Kf, Kh);

    // 4) SIM: E = exp(quant(Qh @ Kh^T)) fp16, den = rowsum (1-term fp16)
    sim1_kernel<<<dim3(A / 128, B / 128), 256, SMEM2T>>>(
        Qh, Kh, H, A, dn, E);

    // 5) OUT: out = (E @ V) / den  (1-term fp16)
    out1_kernel<<<dim3(H / 128, B / 128), 256, SMEM2T>>>(
        E, Vt, A, H, dn, out);
}